// round 1
// baseline (speedup 1.0000x reference)
#include <cuda_runtime.h>
#include <math.h>

#define NB    4
#define NTOK  1024
#define DI    384
#define SS    16
#define KDIM  384
#define NOUT  832            // 384 + 384 + 16 + 16 + 16, padded to 13*64
#define DT_MAX_F 0.15f

#define SSM_SMEM_FLOATS (3*SS*NTOK + 32)
#define SSM_SMEM_BYTES  (SSM_SMEM_FLOATS * 4)

// ---------------- device scratch (no allocations allowed) ----------------
__device__ __align__(16) float g_Wcat[NOUT*KDIM];
__device__ __align__(16) float g_bias[NOUT];
__device__ __align__(16) float g_dsT[NB*DI*NTOK];   // (B,D,N) transposed deltas
__device__ __align__(16) float g_ddT[NB*DI*NTOK];
__device__ __align__(16) float g_Bm [NB*NTOK*SS];   // (B,N,S)
__device__ __align__(16) float g_Cr [NB*NTOK*SS];
__device__ __align__(16) float g_Ci [NB*NTOK*SS];
__device__ __align__(16) float g_xT [NB*DI*NTOK];   // (B,D,N)

__device__ __forceinline__ float softplusf(float z){
  return (z > 0.f) ? (z + log1pf(expf(-z))) : log1pf(expf(z));
}

// ---------------- pack concatenated weight matrix (K-major) ----------------
__global__ void pack_kernel(const float* __restrict__ sW, const float* __restrict__ sb,
                            const float* __restrict__ dW, const float* __restrict__ db,
                            const float* __restrict__ BW, const float* __restrict__ CrW,
                            const float* __restrict__ CiW){
  int j = blockIdx.x;      // 0..831
  int k = threadIdx.x;     // 0..383
  float v;
  if      (j < 384) v = sW[j*KDIM + k];
  else if (j < 768) v = dW[(j-384)*KDIM + k];
  else if (j < 784) v = BW [k*SS + (j-768)];
  else if (j < 800) v = CrW[k*SS + (j-784)];
  else if (j < 816) v = CiW[k*SS + (j-800)];
  else              v = 0.f;
  g_Wcat[(size_t)j*KDIM + k] = v;
  if (k == 0){
    float bv = 0.f;
    if      (j < 384) bv = sb[j];
    else if (j < 768) bv = db[j-384];
    g_bias[j] = bv;
  }
}

// ---------------- transpose x: (B,N,D) -> (B,D,N) ----------------
__global__ void transpose_x_kernel(const float* __restrict__ x){
  __shared__ float tile[32][33];
  int b  = blockIdx.z;
  int d0 = blockIdx.x * 32;
  int n0 = blockIdx.y * 32;
  int tx = threadIdx.x, ty = threadIdx.y;   // (32,8)
  #pragma unroll
  for (int r = 0; r < 32; r += 8)
    tile[ty+r][tx] = x[((size_t)b*NTOK + n0+ty+r)*DI + d0+tx];
  __syncthreads();
  #pragma unroll
  for (int r = 0; r < 32; r += 8)
    g_xT[((size_t)b*DI + d0+ty+r)*NTOK + n0+tx] = tile[tx][ty+r];
}

// ---------------- fused projection GEMM: out = x @ Wcat^T + bias ----------------
// C[m][j] = sum_k X[m][k]*Wcat[j][k];  epilogue splits columns into
// delta_s / delta_d (softplus+clamp, transposed store) and B/C matrices.
__global__ __launch_bounds__(256) void gemm_kernel(const float* __restrict__ X){
  __shared__ float As[16][132];   // [k][m], pad 4 to cut store conflicts, keep 16B align
  __shared__ float Bs[16][68];    // [k][j]
  int tid = threadIdx.x;
  int j0 = blockIdx.x * 64;
  int m0 = blockIdx.y * 128;
  int tx = tid & 15;            // 16 col groups of 4
  int ty = tid >> 4;            // 16 row groups of 8
  int lrow = tid >> 2;          // 0..63
  int lk   = (tid & 3) * 4;     // 0,4,8,12

  float acc[8][4];
  #pragma unroll
  for (int r = 0; r < 8; r++)
    #pragma unroll
    for (int c = 0; c < 4; c++) acc[r][c] = 0.f;

  for (int k0 = 0; k0 < KDIM; k0 += 16){
    float4 a0 = *(const float4*)&X[(size_t)(m0+lrow)    *KDIM + k0 + lk];
    float4 a1 = *(const float4*)&X[(size_t)(m0+lrow+64) *KDIM + k0 + lk];
    float4 bv = *(const float4*)&g_Wcat[(size_t)(j0+lrow)*KDIM + k0 + lk];
    __syncthreads();
    As[lk+0][lrow]    = a0.x; As[lk+1][lrow]    = a0.y; As[lk+2][lrow]    = a0.z; As[lk+3][lrow]    = a0.w;
    As[lk+0][lrow+64] = a1.x; As[lk+1][lrow+64] = a1.y; As[lk+2][lrow+64] = a1.z; As[lk+3][lrow+64] = a1.w;
    Bs[lk+0][lrow]    = bv.x; Bs[lk+1][lrow]    = bv.y; Bs[lk+2][lrow]    = bv.z; Bs[lk+3][lrow]    = bv.w;
    __syncthreads();
    #pragma unroll
    for (int kk = 0; kk < 16; kk++){
      float4 av0 = *(const float4*)&As[kk][ty*8];
      float4 av1 = *(const float4*)&As[kk][ty*8+4];
      float4 bb  = *(const float4*)&Bs[kk][tx*4];
      float a[8] = {av0.x,av0.y,av0.z,av0.w, av1.x,av1.y,av1.z,av1.w};
      float bl[4]= {bb.x, bb.y, bb.z, bb.w};
      #pragma unroll
      for (int r = 0; r < 8; r++)
        #pragma unroll
        for (int c = 0; c < 4; c++)
          acc[r][c] = fmaf(a[r], bl[c], acc[r][c]);
    }
  }

  #pragma unroll
  for (int r = 0; r < 8; r++){
    int m  = m0 + ty*8 + r;
    int b  = m >> 10;
    int nn = m & 1023;
    #pragma unroll
    for (int c = 0; c < 4; c++){
      int j = j0 + tx*4 + c;
      float v = acc[r][c] + g_bias[j];
      if      (j < 384) g_dsT[((size_t)b*DI + j      )*NTOK + nn] = fminf(softplusf(v), DT_MAX_F);
      else if (j < 768) g_ddT[((size_t)b*DI + (j-384))*NTOK + nn] = fminf(softplusf(v), DT_MAX_F);
      else if (j < 784) g_Bm [((size_t)b*NTOK + nn)*SS + (j-768)] = v;
      else if (j < 800) g_Cr [((size_t)b*NTOK + nn)*SS + (j-784)] = v;
      else if (j < 816) g_Ci [((size_t)b*NTOK + nn)*SS + (j-800)] = v;
      // j >= 816: padding, discard
    }
  }
}

// ---------------- fused SSM kernel: one CTA per (b,d); whole state in SMEM ----------------
// Thread t owns a 4-wide spatial strip: i = t>>3 (row 0..31), j0 = (t&7)*4.
__global__ __launch_bounds__(256) void ssm_kernel(
    const float* __restrict__ A_log, const float* __restrict__ conv_w,
    const float* __restrict__ alpha_g, const float* __restrict__ beta_g,
    const float* __restrict__ Dp_g, float* __restrict__ y)
{
  extern __shared__ float sh[];
  float* shr = sh;                 // h_real [SS][NTOK]
  float* shi = sh +     SS*NTOK;   // h_imag
  float* shB = sh + 2 * SS*NTOK;   // B_mat slab, later reused for C_real / C_imag
  float* shA = sh + 3 * SS*NTOK;   // A[s] (16)

  int tid = threadIdx.x;
  int bd  = blockIdx.x;
  int b = bd / DI, d = bd - b*DI;
  int i  = tid >> 3;
  int j0 = (tid & 7) << 2;
  int n0 = (i << 5) + j0;

  float cw[9];
  #pragma unroll
  for (int k = 0; k < 9; k++) cw[k] = conv_w[d*9 + k];
  float alpha = alpha_g[d];
  float beta  = beta_g[d];
  float Dp    = Dp_g[d];

  float4 t4;
  t4 = *(const float4*)&g_xT [(size_t)bd*NTOK + n0];
  float xr[4]  = {t4.x, t4.y, t4.z, t4.w};
  t4 = *(const float4*)&g_dsT[(size_t)bd*NTOK + n0];
  float dsv[4] = {t4.x, t4.y, t4.z, t4.w};
  t4 = *(const float4*)&g_ddT[(size_t)bd*NTOK + n0];
  float ddv[4] = {t4.x, t4.y, t4.z, t4.w};

  if (tid < SS) shA[tid] = -softplusf(A_log[d*SS + tid]);

  // Stage B_mat (B,N,S) -> shB[s][n]; coalesced global float4 reads.
  {
    const float4* src = (const float4*)(g_Bm + (size_t)b*NTOK*SS);
    #pragma unroll
    for (int q = 0; q < 16; q++){
      int fl4 = tid + q*256;
      float4 v = src[fl4];
      int n  = fl4 >> 2;
      int s0 = (fl4 & 3) << 2;
      shB[(s0+0)*NTOK + n] = v.x;
      shB[(s0+1)*NTOK + n] = v.y;
      shB[(s0+2)*NTOK + n] = v.z;
      shB[(s0+3)*NTOK + n] = v.w;
    }
  }
  __syncthreads();

  // h_real = mamba_input = x * B_mat ; h_imag = 0
  #pragma unroll
  for (int s = 0; s < SS; s++){
    float4 bm = *(const float4*)&shB[s*NTOK + n0];
    *(float4*)&shr[s*NTOK + n0] = make_float4(xr[0]*bm.x, xr[1]*bm.y, xr[2]*bm.z, xr[3]*bm.w);
    *(float4*)&shi[s*NTOK + n0] = make_float4(0.f, 0.f, 0.f, 0.f);
  }
  __syncthreads();

  // replicate-padded row / edge-col indices (fixed per thread)
  int rowm = ((i > 0)  ? i-1 : 0 ) << 5;
  int row0 = i << 5;
  int rowp = ((i < 31) ? i+1 : 31) << 5;
  int cl   = (j0 > 0)  ? j0-1 : 0;
  int cr2  = (j0 < 28) ? j0+4 : 31;

  for (int step = 0; step < 2; step++){
    for (int s = 0; s < SS; s++){
      const float* hr = shr + s*NTOK;
      const float* hi = shi + s*NTOK;
      float As = shA[s];
      float wR[3][6], wI[3][6];
      {
        float4 v;
        v = *(const float4*)(hr + rowm + j0);
        wR[0][1]=v.x; wR[0][2]=v.y; wR[0][3]=v.z; wR[0][4]=v.w;
        wR[0][0]=hr[rowm+cl]; wR[0][5]=hr[rowm+cr2];
        v = *(const float4*)(hr + row0 + j0);
        wR[1][1]=v.x; wR[1][2]=v.y; wR[1][3]=v.z; wR[1][4]=v.w;
        wR[1][0]=hr[row0+cl]; wR[1][5]=hr[row0+cr2];
        v = *(const float4*)(hr + rowp + j0);
        wR[2][1]=v.x; wR[2][2]=v.y; wR[2][3]=v.z; wR[2][4]=v.w;
        wR[2][0]=hr[rowp+cl]; wR[2][5]=hr[rowp+cr2];

        v = *(const float4*)(hi + rowm + j0);
        wI[0][1]=v.x; wI[0][2]=v.y; wI[0][3]=v.z; wI[0][4]=v.w;
        wI[0][0]=hi[rowm+cl]; wI[0][5]=hi[rowm+cr2];
        v = *(const float4*)(hi + row0 + j0);
        wI[1][1]=v.x; wI[1][2]=v.y; wI[1][3]=v.z; wI[1][4]=v.w;
        wI[1][0]=hi[row0+cl]; wI[1][5]=hi[row0+cr2];
        v = *(const float4*)(hi + rowp + j0);
        wI[2][1]=v.x; wI[2][2]=v.y; wI[2][3]=v.z; wI[2][4]=v.w;
        wI[2][0]=hi[rowp+cl]; wI[2][5]=hi[rowp+cr2];
      }
      float4 bm = *(const float4*)&shB[s*NTOK + n0];
      float bmv[4] = {bm.x, bm.y, bm.z, bm.w};
      float nhr[4], nhi[4];
      #pragma unroll
      for (int p = 0; p < 4; p++){
        float lr = 0.f, li = 0.f;
        #pragma unroll
        for (int ky = 0; ky < 3; ky++){
          lr = fmaf(cw[ky*3+0], wR[ky][p+0], lr);
          lr = fmaf(cw[ky*3+1], wR[ky][p+1], lr);
          lr = fmaf(cw[ky*3+2], wR[ky][p+2], lr);
          li = fmaf(cw[ky*3+0], wI[ky][p+0], li);
          li = fmaf(cw[ky*3+1], wI[ky][p+1], li);
          li = fmaf(cw[ky*3+2], wI[ky][p+2], li);
        }
        float h_r = wR[1][p+1], h_i = wI[1][p+1];
        float f1r = dsv[p] * fmaf(As, h_r, xr[p]*bmv[p]);
        float f1i = dsv[p] * (As * h_i);
        float f2r = -ddv[p] * li;
        float f2i =  ddv[p] * lr;
        float rs  = alpha - beta * fmaf(h_r, h_r, h_i*h_i);
        nhr[p] = fmaf(0.5f, fmaf(h_r, rs, f1r + f2r), h_r);
        nhi[p] = fmaf(0.5f, fmaf(h_i, rs, f1i + f2i), h_i);
      }
      __syncthreads();   // all reads of state s done before anyone writes it
      *(float4*)&shr[s*NTOK + n0] = make_float4(nhr[0], nhr[1], nhr[2], nhr[3]);
      *(float4*)&shi[s*NTOK + n0] = make_float4(nhi[0], nhi[1], nhi[2], nhi[3]);
    }
  }
  __syncthreads();

  // epilogue: y = sum_s hr*Cr + hi*Ci + x*D
  float acc[4] = {xr[0]*Dp, xr[1]*Dp, xr[2]*Dp, xr[3]*Dp};
  {
    const float4* src = (const float4*)(g_Cr + (size_t)b*NTOK*SS);
    #pragma unroll
    for (int q = 0; q < 16; q++){
      int fl4 = tid + q*256;
      float4 v = src[fl4];
      int n  = fl4 >> 2;
      int s0 = (fl4 & 3) << 2;
      shB[(s0+0)*NTOK + n] = v.x;
      shB[(s0+1)*NTOK + n] = v.y;
      shB[(s0+2)*NTOK + n] = v.z;
      shB[(s0+3)*NTOK + n] = v.w;
    }
  }
  __syncthreads();
  #pragma unroll
  for (int s = 0; s < SS; s++){
    float4 h4 = *(const float4*)&shr[s*NTOK + n0];
    float4 c4 = *(const float4*)&shB[s*NTOK + n0];
    acc[0] = fmaf(h4.x, c4.x, acc[0]);
    acc[1] = fmaf(h4.y, c4.y, acc[1]);
    acc[2] = fmaf(h4.z, c4.z, acc[2]);
    acc[3] = fmaf(h4.w, c4.w, acc[3]);
  }
  __syncthreads();
  {
    const float4* src = (const float4*)(g_Ci + (size_t)b*NTOK*SS);
    #pragma unroll
    for (int q = 0; q < 16; q++){
      int fl4 = tid + q*256;
      float4 v = src[fl4];
      int n  = fl4 >> 2;
      int s0 = (fl4 & 3) << 2;
      shB[(s0+0)*NTOK + n] = v.x;
      shB[(s0+1)*NTOK + n] = v.y;
      shB[(s0+2)*NTOK + n] = v.z;
      shB[(s0+3)*NTOK + n] = v.w;
    }
  }
  __syncthreads();
  #pragma unroll
  for (int s = 0; s < SS; s++){
    float4 h4 = *(const float4*)&shi[s*NTOK + n0];
    float4 c4 = *(const float4*)&shB[s*NTOK + n0];
    acc[0] = fmaf(h4.x, c4.x, acc[0]);
    acc[1] = fmaf(h4.y, c4.y, acc[1]);
    acc[2] = fmaf(h4.z, c4.z, acc[2]);
    acc[3] = fmaf(h4.w, c4.w, acc[3]);
  }
  #pragma unroll
  for (int p = 0; p < 4; p++)
    y[((size_t)b*NTOK + n0 + p)*DI + d] = acc[p];
}

// ---------------- launch ----------------
extern "C" void kernel_launch(void* const* d_in, const int* in_sizes, int n_in,
                              void* d_out, int out_size) {
  const float* x    = (const float*)d_in[0];
  const float* sW   = (const float*)d_in[1];
  const float* sb   = (const float*)d_in[2];
  const float* dW   = (const float*)d_in[3];
  const float* db   = (const float*)d_in[4];
  const float* BW   = (const float*)d_in[5];
  const float* CrW  = (const float*)d_in[6];
  const float* CiW  = (const float*)d_in[7];
  const float* Dpar = (const float*)d_in[8];
  const float* Alog = (const float*)d_in[9];
  const float* cwp  = (const float*)d_in[10];
  const float* ra   = (const float*)d_in[11];
  const float* rb   = (const float*)d_in[12];
  float* y = (float*)d_out;

  cudaFuncSetAttribute(ssm_kernel, cudaFuncAttributeMaxDynamicSharedMemorySize,
                       SSM_SMEM_BYTES);

  pack_kernel<<<NOUT, KDIM>>>(sW, sb, dW, db, BW, CrW, CiW);
  transpose_x_kernel<<<dim3(12, 32, 4), dim3(32, 8)>>>(x);
  gemm_kernel<<<dim3(13, 32), 256>>>(x);
  ssm_kernel<<<NB*DI, 256, SSM_SMEM_BYTES>>>(Alog, cwp, ra, rb, Dpar, y);
}

// round 13
// speedup vs baseline: 1.0383x; 1.0383x over previous
#include <cuda_runtime.h>
#include <math.h>

#define NB    4
#define NTOK  1024
#define DI    384
#define SS    16
#define KDIM  384
#define NOUT  832            // 384 + 384 + 16 + 16 + 16, padded to 13*64
#define DT_MAX_F 0.15f
#define PADR  36             // padded row stride (floats) for conflict-free lane-strided LDS

// ---------------- device scratch (no allocations allowed) ----------------
__device__ __align__(16) float g_Wcat[NOUT*KDIM];
__device__ __align__(16) float g_bias[NOUT];
__device__ __align__(16) float g_dsT[NB*DI*NTOK];   // (B,D,N)
__device__ __align__(16) float g_ddT[NB*DI*NTOK];   // (B,D,N)
__device__ __align__(16) float g_BmT[NB*SS*NTOK];   // (B,S,N) transposed
__device__ __align__(16) float g_CrT[NB*SS*NTOK];   // (B,S,N)
__device__ __align__(16) float g_CiT[NB*SS*NTOK];   // (B,S,N)
__device__ __align__(16) float g_xT [NB*DI*NTOK];   // (B,D,N)

__device__ __forceinline__ float softplusf(float z){
  return (z > 0.f) ? (z + log1pf(expf(-z))) : log1pf(expf(z));
}

// ---- f32x2 packed helpers (Blackwell FFMA2 — only reachable via PTX) ----
typedef unsigned long long u64;
__device__ __forceinline__ u64 pack2(float lo, float hi){
  u64 d; asm("mov.b64 %0, {%1, %2};" : "=l"(d) : "f"(lo), "f"(hi)); return d;
}
__device__ __forceinline__ void unpack2(u64 v, float& lo, float& hi){
  asm("mov.b64 {%0, %1}, %2;" : "=f"(lo), "=f"(hi) : "l"(v));
}
__device__ __forceinline__ u64 ffma2(u64 a, u64 b, u64 c){
  u64 d; asm("fma.rn.f32x2 %0, %1, %2, %3;" : "=l"(d) : "l"(a), "l"(b), "l"(c)); return d;
}
__device__ __forceinline__ u64 fmul2(u64 a, u64 b){
  u64 d; asm("mul.rn.f32x2 %0, %1, %2;" : "=l"(d) : "l"(a), "l"(b)); return d;
}
union U2 { u64 u; float2 f; };

// ---------------- pack concatenated weight matrix (K-major) ----------------
__global__ void pack_kernel(const float* __restrict__ sW, const float* __restrict__ sb,
                            const float* __restrict__ dW, const float* __restrict__ db,
                            const float* __restrict__ BW, const float* __restrict__ CrW,
                            const float* __restrict__ CiW){
  int j = blockIdx.x;      // 0..831
  int k = threadIdx.x;     // 0..383
  float v;
  if      (j < 384) v = sW[j*KDIM + k];
  else if (j < 768) v = dW[(j-384)*KDIM + k];
  else if (j < 784) v = BW [k*SS + (j-768)];
  else if (j < 800) v = CrW[k*SS + (j-784)];
  else if (j < 816) v = CiW[k*SS + (j-800)];
  else              v = 0.f;
  g_Wcat[(size_t)j*KDIM + k] = v;
  if (k == 0){
    float bv = 0.f;
    if      (j < 384) bv = sb[j];
    else if (j < 768) bv = db[j-384];
    g_bias[j] = bv;
  }
}

// ---------------- transpose x: (B,N,D) -> (B,D,N) ----------------
__global__ void transpose_x_kernel(const float* __restrict__ x){
  __shared__ float tile[32][33];
  int b  = blockIdx.z;
  int d0 = blockIdx.x * 32;
  int n0 = blockIdx.y * 32;
  int tx = threadIdx.x, ty = threadIdx.y;   // (32,8)
  #pragma unroll
  for (int r = 0; r < 32; r += 8)
    tile[ty+r][tx] = x[((size_t)b*NTOK + n0+ty+r)*DI + d0+tx];
  __syncthreads();
  #pragma unroll
  for (int r = 0; r < 32; r += 8)
    g_xT[((size_t)b*DI + d0+ty+r)*NTOK + n0+tx] = tile[tx][ty+r];
}

// ---------------- fused projection GEMM (f32x2 inner loop) ----------------
__global__ __launch_bounds__(256) void gemm_kernel(const float* __restrict__ X){
  __shared__ __align__(16) float As[16][132];   // [k][m]
  __shared__ __align__(16) float Bs[16][68];    // [k][j]
  int tid = threadIdx.x;
  int j0 = blockIdx.x * 64;
  int m0 = blockIdx.y * 128;
  int tx = tid & 15;            // 16 col groups of 4
  int ty = tid >> 4;            // 16 row groups of 8
  int lrow = tid >> 2;          // 0..63
  int lk   = (tid & 3) * 4;     // 0,4,8,12

  u64 acc2[4][4];               // row-pairs (2rp,2rp+1) x 4 cols
  #pragma unroll
  for (int rp = 0; rp < 4; rp++)
    #pragma unroll
    for (int c = 0; c < 4; c++) acc2[rp][c] = pack2(0.f, 0.f);

  for (int k0 = 0; k0 < KDIM; k0 += 16){
    float4 a0 = *(const float4*)&X[(size_t)(m0+lrow)    *KDIM + k0 + lk];
    float4 a1 = *(const float4*)&X[(size_t)(m0+lrow+64) *KDIM + k0 + lk];
    float4 bv = *(const float4*)&g_Wcat[(size_t)(j0+lrow)*KDIM + k0 + lk];
    __syncthreads();
    As[lk+0][lrow]    = a0.x; As[lk+1][lrow]    = a0.y; As[lk+2][lrow]    = a0.z; As[lk+3][lrow]    = a0.w;
    As[lk+0][lrow+64] = a1.x; As[lk+1][lrow+64] = a1.y; As[lk+2][lrow+64] = a1.z; As[lk+3][lrow+64] = a1.w;
    Bs[lk+0][lrow]    = bv.x; Bs[lk+1][lrow]    = bv.y; Bs[lk+2][lrow]    = bv.z; Bs[lk+3][lrow]    = bv.w;
    __syncthreads();
    #pragma unroll
    for (int kk = 0; kk < 16; kk++){
      const ulonglong2 ap0 = *(const ulonglong2*)&As[kk][ty*8];
      const ulonglong2 ap1 = *(const ulonglong2*)&As[kk][ty*8+4];
      u64 a2[4] = {ap0.x, ap0.y, ap1.x, ap1.y};
      float4 bb = *(const float4*)&Bs[kk][tx*4];
      u64 b2[4] = {pack2(bb.x,bb.x), pack2(bb.y,bb.y),
                   pack2(bb.z,bb.z), pack2(bb.w,bb.w)};
      #pragma unroll
      for (int rp = 0; rp < 4; rp++)
        #pragma unroll
        for (int c = 0; c < 4; c++)
          acc2[rp][c] = ffma2(a2[rp], b2[c], acc2[rp][c]);
    }
  }

  #pragma unroll
  for (int rp = 0; rp < 4; rp++){
    #pragma unroll
    for (int half = 0; half < 2; half++){
      int m  = m0 + ty*8 + rp*2 + half;
      int b  = m >> 10;
      int nn = m & 1023;
      #pragma unroll
      for (int c = 0; c < 4; c++){
        U2 u; u.u = acc2[rp][c];
        float v = (half ? u.f.y : u.f.x);
        int j = j0 + tx*4 + c;
        v += g_bias[j];
        if      (j < 384) g_dsT[((size_t)b*DI + j      )*NTOK + nn] = fminf(softplusf(v), DT_MAX_F);
        else if (j < 768) g_ddT[((size_t)b*DI + (j-384))*NTOK + nn] = fminf(softplusf(v), DT_MAX_F);
        else if (j < 784) g_BmT[((size_t)b*SS + (j-768))*NTOK + nn] = v;
        else if (j < 800) g_CrT[((size_t)b*SS + (j-784))*NTOK + nn] = v;
        else if (j < 816) g_CiT[((size_t)b*SS + (j-800))*NTOK + nn] = v;
      }
    }
  }
}

// ---------------- SSM: warp = state, lane = row; packed (re,im) state in regs ----------------
#define SSM_SMEM_FLOATS (SS*32*PADR + 2*32*PADR)
#define SSM_SMEM_BYTES  (SSM_SMEM_FLOATS * 4)

__global__ __launch_bounds__(512) void ssm_kernel(
    const float* __restrict__ A_log, const float* __restrict__ conv_w,
    const float* __restrict__ alpha_g, const float* __restrict__ beta_g,
    const float* __restrict__ Dp_g, float* __restrict__ y)
{
  extern __shared__ float sh[];
  float* s_dsmp = sh;                       // [SS][32*PADR]  ds*x*bm (per state)
  float* s_ds   = sh + SS*32*PADR;          // [32*PADR]
  float* s_dd   = s_ds + 32*PADR;           // [32*PADR]

  int tid = threadIdx.x;
  int s   = tid >> 5;     // warp id = state
  int r   = tid & 31;     // lane    = grid row
  int bd  = blockIdx.x;
  int b = bd / DI, d = bd - b*DI;

  u64 cw2[9];
  #pragma unroll
  for (int k = 0; k < 9; k++){ float w = conv_w[d*9 + k]; cw2[k] = pack2(w, w); }
  float A     = -softplusf(A_log[d*SS + s]);
  float alpha = alpha_g[d];
  float beta  = beta_g[d];
  const u64 half2 = pack2(0.5f, 0.5f);

  const float* xrow  = g_xT  + (size_t)bd*NTOK + r*32;
  const float* dsrow = g_dsT + (size_t)bd*NTOK + r*32;
  const float* ddrow = g_ddT + (size_t)bd*NTOK + r*32;
  const float* bmrow = g_BmT + ((size_t)b*SS + s)*NTOK + r*32;

  u64 h2[32];                               // packed (re, im) per column
  float* dsm = s_dsmp + s*32*PADR + r*PADR;

  // ---- init: h = (x*bm, 0), dsmp = ds*x*bm; warp0 publishes ds/dd rows ----
  #pragma unroll
  for (int q = 0; q < 8; q++){
    float4 xv  = *(const float4*)(xrow  + 4*q);
    float4 bv  = *(const float4*)(bmrow + 4*q);
    float4 dsv = *(const float4*)(dsrow + 4*q);
    float m0 = xv.x*bv.x, m1 = xv.y*bv.y, m2 = xv.z*bv.z, m3 = xv.w*bv.w;
    h2[4*q+0] = pack2(m0, 0.f);
    h2[4*q+1] = pack2(m1, 0.f);
    h2[4*q+2] = pack2(m2, 0.f);
    h2[4*q+3] = pack2(m3, 0.f);
    *(float4*)(dsm + 4*q) = make_float4(dsv.x*m0, dsv.y*m1, dsv.z*m2, dsv.w*m3);
    if (s == 0){
      float4 ddv = *(const float4*)(ddrow + 4*q);
      *(float4*)(s_ds + r*PADR + 4*q) = dsv;
      *(float4*)(s_dd + r*PADR + 4*q) = ddv;
    }
  }
  __syncthreads();

  const float* dsp = s_ds + r*PADR;
  const float* ddp = s_dd + r*PADR;

  // ---- K_steps evolution: registers + shuffles only ----
  #pragma unroll 1
  for (int step = 0; step < 2; step++){
    // sliding windows for rows r-1 (up) and r+1 (dn); shfl clamps = replicate pad
    u64 upC = __shfl_up_sync  (0xffffffffu, h2[0], 1);
    u64 dnC = __shfl_down_sync(0xffffffffu, h2[0], 1);
    u64 upL = upC, dnL = dnC;
    u64 oldL = h2[0];     // own row col j-1 (old value), replicate at j=0

    #pragma unroll
    for (int j0 = 0; j0 < 8; j0++){
      float4 ds4 = *(const float4*)(dsp + 4*j0);
      float4 dd4 = *(const float4*)(ddp + 4*j0);
      float4 dm4 = *(const float4*)(dsm + 4*j0);
      float dsa[4] = {ds4.x, ds4.y, ds4.z, ds4.w};
      float dda[4] = {dd4.x, dd4.y, dd4.z, dd4.w};
      float dma[4] = {dm4.x, dm4.y, dm4.z, dm4.w};
      #pragma unroll
      for (int jj = 0; jj < 4; jj++){
        const int j = j0*4 + jj;
        u64 rv  = h2[(j < 31) ? j+1 : 31];        // own row col j+1 (old; replicate at 31)
        u64 upR = __shfl_up_sync  (0xffffffffu, rv, 1);
        u64 dnR = __shfl_down_sync(0xffffffffu, rv, 1);
        u64 cur = h2[j];

        // 3x3 correlation, both fields at once (replicate-padded)
        u64 lap = fmul2(cw2[0], upL);
        lap = ffma2(cw2[1], upC,  lap);
        lap = ffma2(cw2[2], upR,  lap);
        lap = ffma2(cw2[3], oldL, lap);
        lap = ffma2(cw2[4], cur,  lap);
        lap = ffma2(cw2[5], rv,   lap);
        lap = ffma2(cw2[6], dnL,  lap);
        lap = ffma2(cw2[7], dnC,  lap);
        lap = ffma2(cw2[8], dnR,  lap);

        float dsv = dsa[jj], ddv = dda[jj], dmv = dma[jj];
        // f1 = (ds*A)*h + (ds*minp, 0)   [dmv = ds*minp precomputed at init]
        float dsA = dsv * A;
        u64 f1 = ffma2(pack2(dsA, dsA), cur, pack2(dmv, 0.f));
        // f2 = dd * (-lap_im, +lap_re): swap halves, fold sign into dd pair
        float lr, li; unpack2(lap, lr, li);
        u64 g2 = ffma2(pack2(-ddv, ddv), pack2(li, lr), f1);
        // reaction scale (scalar: cross-half reduction)
        float hrv, hiv; unpack2(cur, hrv, hiv);
        float nrm = fmaf(hrv, hrv, hiv*hiv);
        float rs  = fmaf(-beta, nrm, alpha);
        // h += 0.5 * (g2 + h*rs)
        u64 u  = ffma2(cur, pack2(rs, rs), g2);
        h2[j]  = ffma2(half2, u, cur);

        oldL = cur;
        upL = upC; upC = upR;
        dnL = dnC; dnC = dnR;
      }
    }
  }

  // ---- epilogue: per-warp partials p[s][n] = hr*Cr + hi*Ci (reuse dsmp slab) ----
  const float* crrow = g_CrT + ((size_t)b*SS + s)*NTOK + r*32;
  const float* cirow = g_CiT + ((size_t)b*SS + s)*NTOK + r*32;
  #pragma unroll
  for (int q = 0; q < 8; q++){
    float4 cr4 = *(const float4*)(crrow + 4*q);
    float4 ci4 = *(const float4*)(cirow + 4*q);
    float h0r,h0i,h1r,h1i,h2r,h2i,h3r,h3i;
    unpack2(h2[4*q+0], h0r, h0i);
    unpack2(h2[4*q+1], h1r, h1i);
    unpack2(h2[4*q+2], h2r, h2i);
    unpack2(h2[4*q+3], h3r, h3i);
    float4 p;
    p.x = fmaf(h0r, cr4.x, h0i*ci4.x);
    p.y = fmaf(h1r, cr4.y, h1i*ci4.y);
    p.z = fmaf(h2r, cr4.z, h2i*ci4.z);
    p.w = fmaf(h3r, cr4.w, h3i*ci4.w);
    *(float4*)(dsm + 4*q) = p;   // lane-private region, no sync needed
  }
  __syncthreads();

  // reduction over s: each thread handles 2 columns
  {
    int n0 = tid * 2;
    int row = n0 >> 5, col = n0 & 31;
    float a0 = 0.f, a1 = 0.f;
    #pragma unroll
    for (int ss = 0; ss < SS; ss++){
      float2 v = *(const float2*)(s_dsmp + ss*32*PADR + row*PADR + col);
      a0 += v.x; a1 += v.y;
    }
    float Dv = Dp_g[d];
    float2 xv = *(const float2*)(g_xT + (size_t)bd*NTOK + n0);
    y[((size_t)b*NTOK + n0    )*DI + d] = fmaf(xv.x, Dv, a0);
    y[((size_t)b*NTOK + n0 + 1)*DI + d] = fmaf(xv.y, Dv, a1);
  }
}

// ---------------- launch ----------------
extern "C" void kernel_launch(void* const* d_in, const int* in_sizes, int n_in,
                              void* d_out, int out_size) {
  const float* x    = (const float*)d_in[0];
  const float* sW   = (const float*)d_in[1];
  const float* sb   = (const float*)d_in[2];
  const float* dW   = (const float*)d_in[3];
  const float* db   = (const float*)d_in[4];
  const float* BW   = (const float*)d_in[5];
  const float* CrW  = (const float*)d_in[6];
  const float* CiW  = (const float*)d_in[7];
  const float* Dpar = (const float*)d_in[8];
  const float* Alog = (const float*)d_in[9];
  const float* cwp  = (const float*)d_in[10];
  const float* ra   = (const float*)d_in[11];
  const float* rb   = (const float*)d_in[12];
  float* y = (float*)d_out;

  cudaFuncSetAttribute(ssm_kernel, cudaFuncAttributeMaxDynamicSharedMemorySize,
                       SSM_SMEM_BYTES);

  pack_kernel<<<NOUT, KDIM>>>(sW, sb, dW, db, BW, CrW, CiW);
  transpose_x_kernel<<<dim3(12, 32, 4), dim3(32, 8)>>>(x);
  gemm_kernel<<<dim3(13, 32), 256>>>(x);
  ssm_kernel<<<NB*DI, 512, SSM_SMEM_BYTES>>>(Alog, cwp, ra, rb, Dpar, y);
}

// round 17
// speedup vs baseline: 1.1095x; 1.0685x over previous
#include <cuda_runtime.h>
#include <math.h>

#define NB    4
#define NTOK  1024
#define DI    384
#define SS    16
#define KDIM  384
#define NOUT  832            // 384 + 384 + 16 + 16 + 16, padded to 13*64
#define DT_MAX_F 0.15f
#define PADR  36             // padded row stride (floats) for conflict-free lane-strided LDS

// ---------------- device scratch (no allocations allowed) ----------------
__device__ __align__(16) float g_Wcat[NOUT*KDIM];
__device__ __align__(16) float g_bias[NOUT];
__device__ __align__(16) float g_dsT[NB*DI*NTOK];   // (B,D,N)
__device__ __align__(16) float g_ddT[NB*DI*NTOK];   // (B,D,N)
__device__ __align__(16) float g_BmT[NB*SS*NTOK];   // (B,S,N) transposed
__device__ __align__(16) float g_CrT[NB*SS*NTOK];   // (B,S,N)
__device__ __align__(16) float g_CiT[NB*SS*NTOK];   // (B,S,N)
__device__ __align__(16) float g_xT [NB*DI*NTOK];   // (B,D,N)

__device__ __forceinline__ float softplusf(float z){
  return (z > 0.f) ? (z + log1pf(expf(-z))) : log1pf(expf(z));
}

// ---- f32x2 packed helpers (Blackwell FFMA2 — only reachable via PTX) ----
typedef unsigned long long u64;
__device__ __forceinline__ u64 pack2(float lo, float hi){
  u64 d; asm("mov.b64 %0, {%1, %2};" : "=l"(d) : "f"(lo), "f"(hi)); return d;
}
__device__ __forceinline__ void unpack2(u64 v, float& lo, float& hi){
  asm("mov.b64 {%0, %1}, %2;" : "=f"(lo), "=f"(hi) : "l"(v));
}
__device__ __forceinline__ u64 ffma2(u64 a, u64 b, u64 c){
  u64 d; asm("fma.rn.f32x2 %0, %1, %2, %3;" : "=l"(d) : "l"(a), "l"(b), "l"(c)); return d;
}
__device__ __forceinline__ u64 fmul2(u64 a, u64 b){
  u64 d; asm("mul.rn.f32x2 %0, %1, %2;" : "=l"(d) : "l"(a), "l"(b)); return d;
}
union U2 { u64 u; float2 f; };

// ---------------- pack concatenated weight matrix (K-major) ----------------
__global__ void pack_kernel(const float* __restrict__ sW, const float* __restrict__ sb,
                            const float* __restrict__ dW, const float* __restrict__ db,
                            const float* __restrict__ BW, const float* __restrict__ CrW,
                            const float* __restrict__ CiW){
  int j = blockIdx.x;      // 0..831
  int k = threadIdx.x;     // 0..383
  float v;
  if      (j < 384) v = sW[j*KDIM + k];
  else if (j < 768) v = dW[(j-384)*KDIM + k];
  else if (j < 784) v = BW [k*SS + (j-768)];
  else if (j < 800) v = CrW[k*SS + (j-784)];
  else if (j < 816) v = CiW[k*SS + (j-800)];
  else              v = 0.f;
  g_Wcat[(size_t)j*KDIM + k] = v;
  if (k == 0){
    float bv = 0.f;
    if      (j < 384) bv = sb[j];
    else if (j < 768) bv = db[j-384];
    g_bias[j] = bv;
  }
}

// ---------------- transpose x: (B,N,D) -> (B,D,N) ----------------
__global__ void transpose_x_kernel(const float* __restrict__ x){
  __shared__ float tile[32][33];
  int b  = blockIdx.z;
  int d0 = blockIdx.x * 32;
  int n0 = blockIdx.y * 32;
  int tx = threadIdx.x, ty = threadIdx.y;   // (32,8)
  #pragma unroll
  for (int r = 0; r < 32; r += 8)
    tile[ty+r][tx] = x[((size_t)b*NTOK + n0+ty+r)*DI + d0+tx];
  __syncthreads();
  #pragma unroll
  for (int r = 0; r < 32; r += 8)
    g_xT[((size_t)b*DI + d0+ty+r)*NTOK + n0+tx] = tile[tx][ty+r];
}

// ---------------- fused projection GEMM (f32x2 inner loop) ----------------
__global__ __launch_bounds__(256) void gemm_kernel(const float* __restrict__ X){
  __shared__ __align__(16) float As[16][132];   // [k][m]
  __shared__ __align__(16) float Bs[16][68];    // [k][j]
  int tid = threadIdx.x;
  int j0 = blockIdx.x * 64;
  int m0 = blockIdx.y * 128;
  int tx = tid & 15;            // 16 col groups of 4
  int ty = tid >> 4;            // 16 row groups of 8
  int lrow = tid >> 2;          // 0..63
  int lk   = (tid & 3) * 4;     // 0,4,8,12

  u64 acc2[4][4];               // row-pairs (2rp,2rp+1) x 4 cols
  #pragma unroll
  for (int rp = 0; rp < 4; rp++)
    #pragma unroll
    for (int c = 0; c < 4; c++) acc2[rp][c] = pack2(0.f, 0.f);

  for (int k0 = 0; k0 < KDIM; k0 += 16){
    float4 a0 = *(const float4*)&X[(size_t)(m0+lrow)    *KDIM + k0 + lk];
    float4 a1 = *(const float4*)&X[(size_t)(m0+lrow+64) *KDIM + k0 + lk];
    float4 bv = *(const float4*)&g_Wcat[(size_t)(j0+lrow)*KDIM + k0 + lk];
    __syncthreads();
    As[lk+0][lrow]    = a0.x; As[lk+1][lrow]    = a0.y; As[lk+2][lrow]    = a0.z; As[lk+3][lrow]    = a0.w;
    As[lk+0][lrow+64] = a1.x; As[lk+1][lrow+64] = a1.y; As[lk+2][lrow+64] = a1.z; As[lk+3][lrow+64] = a1.w;
    Bs[lk+0][lrow]    = bv.x; Bs[lk+1][lrow]    = bv.y; Bs[lk+2][lrow]    = bv.z; Bs[lk+3][lrow]    = bv.w;
    __syncthreads();
    #pragma unroll
    for (int kk = 0; kk < 16; kk++){
      const ulonglong2 ap0 = *(const ulonglong2*)&As[kk][ty*8];
      const ulonglong2 ap1 = *(const ulonglong2*)&As[kk][ty*8+4];
      u64 a2[4] = {ap0.x, ap0.y, ap1.x, ap1.y};
      float4 bb = *(const float4*)&Bs[kk][tx*4];
      u64 b2[4] = {pack2(bb.x,bb.x), pack2(bb.y,bb.y),
                   pack2(bb.z,bb.z), pack2(bb.w,bb.w)};
      #pragma unroll
      for (int rp = 0; rp < 4; rp++)
        #pragma unroll
        for (int c = 0; c < 4; c++)
          acc2[rp][c] = ffma2(a2[rp], b2[c], acc2[rp][c]);
    }
  }

  #pragma unroll
  for (int rp = 0; rp < 4; rp++){
    #pragma unroll
    for (int half = 0; half < 2; half++){
      int m  = m0 + ty*8 + rp*2 + half;
      int b  = m >> 10;
      int nn = m & 1023;
      #pragma unroll
      for (int c = 0; c < 4; c++){
        U2 u; u.u = acc2[rp][c];
        float v = (half ? u.f.y : u.f.x);
        int j = j0 + tx*4 + c;
        v += g_bias[j];
        if      (j < 384) g_dsT[((size_t)b*DI + j      )*NTOK + nn] = fminf(softplusf(v), DT_MAX_F);
        else if (j < 768) g_ddT[((size_t)b*DI + (j-384))*NTOK + nn] = fminf(softplusf(v), DT_MAX_F);
        else if (j < 784) g_BmT[((size_t)b*SS + (j-768))*NTOK + nn] = v;
        else if (j < 800) g_CrT[((size_t)b*SS + (j-784))*NTOK + nn] = v;
        else if (j < 816) g_CiT[((size_t)b*SS + (j-800))*NTOK + nn] = v;
      }
    }
  }
}

// ---------------- SSM: 8 warps, warp = 2 states (s, s+8); lane = row ----------------
// 256 threads -> 255-reg ceiling; both states' h fully register-resident, no spills.
#define SSM_SMEM_FLOATS (SS*32*PADR + 2*32*PADR)
#define SSM_SMEM_BYTES  (SSM_SMEM_FLOATS * 4)

__global__ __launch_bounds__(256) void ssm_kernel(
    const float* __restrict__ A_log, const float* __restrict__ conv_w,
    const float* __restrict__ alpha_g, const float* __restrict__ beta_g,
    const float* __restrict__ Dp_g, float* __restrict__ y)
{
  extern __shared__ float sh[];
  float* s_dsmp = sh;                       // [SS][32*PADR]  ds*x*bm (per state)
  float* s_ds   = sh + SS*32*PADR;          // [32*PADR]
  float* s_dd   = s_ds + 32*PADR;           // [32*PADR]

  int tid = threadIdx.x;
  int s   = tid >> 5;     // warp id = state pair base (0..7): states s and s+8
  int r   = tid & 31;     // lane    = grid row
  int bd  = blockIdx.x;
  int b = bd / DI, d = bd - b*DI;

  u64 cw2[9];
  #pragma unroll
  for (int k = 0; k < 9; k++){ float w = conv_w[d*9 + k]; cw2[k] = pack2(w, w); }
  float A_a   = -softplusf(A_log[d*SS + s]);
  float A_b   = -softplusf(A_log[d*SS + s + 8]);
  float alpha = alpha_g[d];
  float beta  = beta_g[d];
  const u64 half2 = pack2(0.5f, 0.5f);

  const float* xrow  = g_xT  + (size_t)bd*NTOK + r*32;
  const float* dsrow = g_dsT + (size_t)bd*NTOK + r*32;
  const float* ddrow = g_ddT + (size_t)bd*NTOK + r*32;
  const float* bmrowA = g_BmT + ((size_t)b*SS + s    )*NTOK + r*32;
  const float* bmrowB = g_BmT + ((size_t)b*SS + s + 8)*NTOK + r*32;

  u64 hA[32], hB[32];                       // packed (re, im) per column, 2 states
  float* dsmA = s_dsmp + (s    )*32*PADR + r*PADR;
  float* dsmB = s_dsmp + (s + 8)*32*PADR + r*PADR;

  // ---- init: h = (x*bm, 0), dsmp = ds*x*bm; warp0 publishes ds/dd rows ----
  #pragma unroll
  for (int q = 0; q < 8; q++){
    float4 xv  = *(const float4*)(xrow  + 4*q);
    float4 dsv = *(const float4*)(dsrow + 4*q);
    float4 bvA = *(const float4*)(bmrowA + 4*q);
    float4 bvB = *(const float4*)(bmrowB + 4*q);
    float a0 = xv.x*bvA.x, a1 = xv.y*bvA.y, a2 = xv.z*bvA.z, a3 = xv.w*bvA.w;
    float b0 = xv.x*bvB.x, b1 = xv.y*bvB.y, b2 = xv.z*bvB.z, b3 = xv.w*bvB.w;
    hA[4*q+0] = pack2(a0, 0.f); hA[4*q+1] = pack2(a1, 0.f);
    hA[4*q+2] = pack2(a2, 0.f); hA[4*q+3] = pack2(a3, 0.f);
    hB[4*q+0] = pack2(b0, 0.f); hB[4*q+1] = pack2(b1, 0.f);
    hB[4*q+2] = pack2(b2, 0.f); hB[4*q+3] = pack2(b3, 0.f);
    *(float4*)(dsmA + 4*q) = make_float4(dsv.x*a0, dsv.y*a1, dsv.z*a2, dsv.w*a3);
    *(float4*)(dsmB + 4*q) = make_float4(dsv.x*b0, dsv.y*b1, dsv.z*b2, dsv.w*b3);
    if (s == 0){
      float4 ddv = *(const float4*)(ddrow + 4*q);
      *(float4*)(s_ds + r*PADR + 4*q) = dsv;
      *(float4*)(s_dd + r*PADR + 4*q) = ddv;
    }
  }
  __syncthreads();

  const float* dsp = s_ds + r*PADR;
  const float* ddp = s_dd + r*PADR;

  // ---- K_steps evolution: registers + shuffles only; 2 states interleaved ----
  #pragma unroll 1
  for (int step = 0; step < 2; step++){
    u64 upCA = __shfl_up_sync  (0xffffffffu, hA[0], 1);
    u64 dnCA = __shfl_down_sync(0xffffffffu, hA[0], 1);
    u64 upCB = __shfl_up_sync  (0xffffffffu, hB[0], 1);
    u64 dnCB = __shfl_down_sync(0xffffffffu, hB[0], 1);
    u64 upLA = upCA, dnLA = dnCA, oldLA = hA[0];
    u64 upLB = upCB, dnLB = dnCB, oldLB = hB[0];

    #pragma unroll
    for (int j0 = 0; j0 < 8; j0++){
      float4 ds4  = *(const float4*)(dsp  + 4*j0);
      float4 dd4  = *(const float4*)(ddp  + 4*j0);
      float4 dmA4 = *(const float4*)(dsmA + 4*j0);
      float4 dmB4 = *(const float4*)(dsmB + 4*j0);
      float dsa[4]  = {ds4.x, ds4.y, ds4.z, ds4.w};
      float dda[4]  = {dd4.x, dd4.y, dd4.z, dd4.w};
      float dmaA[4] = {dmA4.x, dmA4.y, dmA4.z, dmA4.w};
      float dmaB[4] = {dmB4.x, dmB4.y, dmB4.z, dmB4.w};
      #pragma unroll
      for (int jj = 0; jj < 4; jj++){
        const int j = j0*4 + jj;
        const int jn = (j < 31) ? j+1 : 31;
        u64 rvA = hA[jn], rvB = hB[jn];
        u64 upRA = __shfl_up_sync  (0xffffffffu, rvA, 1);
        u64 dnRA = __shfl_down_sync(0xffffffffu, rvA, 1);
        u64 upRB = __shfl_up_sync  (0xffffffffu, rvB, 1);
        u64 dnRB = __shfl_down_sync(0xffffffffu, rvB, 1);
        u64 curA = hA[j], curB = hB[j];

        u64 lapA = fmul2(cw2[0], upLA);
        u64 lapB = fmul2(cw2[0], upLB);
        lapA = ffma2(cw2[1], upCA,  lapA);  lapB = ffma2(cw2[1], upCB,  lapB);
        lapA = ffma2(cw2[2], upRA,  lapA);  lapB = ffma2(cw2[2], upRB,  lapB);
        lapA = ffma2(cw2[3], oldLA, lapA);  lapB = ffma2(cw2[3], oldLB, lapB);
        lapA = ffma2(cw2[4], curA,  lapA);  lapB = ffma2(cw2[4], curB,  lapB);
        lapA = ffma2(cw2[5], rvA,   lapA);  lapB = ffma2(cw2[5], rvB,   lapB);
        lapA = ffma2(cw2[6], dnLA,  lapA);  lapB = ffma2(cw2[6], dnLB,  lapB);
        lapA = ffma2(cw2[7], dnCA,  lapA);  lapB = ffma2(cw2[7], dnCB,  lapB);
        lapA = ffma2(cw2[8], dnRA,  lapA);  lapB = ffma2(cw2[8], dnRB,  lapB);

        float dsv = dsa[jj], ddv = dda[jj];
        // f1 = (ds*A)*h + (ds*minp, 0)
        float dsAa = dsv * A_a, dsAb = dsv * A_b;
        u64 f1A = ffma2(pack2(dsAa, dsAa), curA, pack2(dmaA[jj], 0.f));
        u64 f1B = ffma2(pack2(dsAb, dsAb), curB, pack2(dmaB[jj], 0.f));
        // f2 = dd * (-lap_im, +lap_re)
        u64 ddpm = pack2(-ddv, ddv);
        float lrA, liA; unpack2(lapA, lrA, liA);
        float lrB, liB; unpack2(lapB, lrB, liB);
        u64 g2A = ffma2(ddpm, pack2(liA, lrA), f1A);
        u64 g2B = ffma2(ddpm, pack2(liB, lrB), f1B);
        // reaction scale
        float hrA, hiA; unpack2(curA, hrA, hiA);
        float hrB, hiB; unpack2(curB, hrB, hiB);
        float rsA = fmaf(-beta, fmaf(hrA, hrA, hiA*hiA), alpha);
        float rsB = fmaf(-beta, fmaf(hrB, hrB, hiB*hiB), alpha);
        // h += 0.5 * (g2 + h*rs)
        u64 uA = ffma2(curA, pack2(rsA, rsA), g2A);
        u64 uB = ffma2(curB, pack2(rsB, rsB), g2B);
        hA[j] = ffma2(half2, uA, curA);
        hB[j] = ffma2(half2, uB, curB);

        oldLA = curA;  oldLB = curB;
        upLA = upCA; upCA = upRA;  upLB = upCB; upCB = upRB;
        dnLA = dnCA; dnCA = dnRA;  dnLB = dnCB; dnCB = dnRB;
      }
    }
  }

  // ---- epilogue: per-state partials p[s][n] = hr*Cr + hi*Ci (reuse dsmp slab) ----
  {
    const float* crA = g_CrT + ((size_t)b*SS + s    )*NTOK + r*32;
    const float* ciA = g_CiT + ((size_t)b*SS + s    )*NTOK + r*32;
    const float* crB = g_CrT + ((size_t)b*SS + s + 8)*NTOK + r*32;
    const float* ciB = g_CiT + ((size_t)b*SS + s + 8)*NTOK + r*32;
    #pragma unroll
    for (int q = 0; q < 8; q++){
      float4 c0 = *(const float4*)(crA + 4*q);
      float4 c1 = *(const float4*)(ciA + 4*q);
      float h0r,h0i,h1r,h1i,h2r,h2i,h3r,h3i;
      unpack2(hA[4*q+0], h0r, h0i); unpack2(hA[4*q+1], h1r, h1i);
      unpack2(hA[4*q+2], h2r, h2i); unpack2(hA[4*q+3], h3r, h3i);
      float4 p;
      p.x = fmaf(h0r, c0.x, h0i*c1.x);
      p.y = fmaf(h1r, c0.y, h1i*c1.y);
      p.z = fmaf(h2r, c0.z, h2i*c1.z);
      p.w = fmaf(h3r, c0.w, h3i*c1.w);
      *(float4*)(dsmA + 4*q) = p;

      float4 c2 = *(const float4*)(crB + 4*q);
      float4 c3 = *(const float4*)(ciB + 4*q);
      unpack2(hB[4*q+0], h0r, h0i); unpack2(hB[4*q+1], h1r, h1i);
      unpack2(hB[4*q+2], h2r, h2i); unpack2(hB[4*q+3], h3r, h3i);
      p.x = fmaf(h0r, c2.x, h0i*c3.x);
      p.y = fmaf(h1r, c2.y, h1i*c3.y);
      p.z = fmaf(h2r, c2.z, h2i*c3.z);
      p.w = fmaf(h3r, c2.w, h3i*c3.w);
      *(float4*)(dsmB + 4*q) = p;
    }
  }
  __syncthreads();

  // reduction over s: each thread handles 4 columns (256 threads x 4 = 1024)
  {
    int n0 = tid * 4;
    int row = n0 >> 5, col = n0 & 31;
    float a0 = 0.f, a1 = 0.f, a2 = 0.f, a3 = 0.f;
    #pragma unroll
    for (int ss = 0; ss < SS; ss++){
      float4 v = *(const float4*)(s_dsmp + ss*32*PADR + row*PADR + col);
      a0 += v.x; a1 += v.y; a2 += v.z; a3 += v.w;
    }
    float Dv = Dp_g[d];
    float4 xv = *(const float4*)(g_xT + (size_t)bd*NTOK + n0);
    y[((size_t)b*NTOK + n0    )*DI + d] = fmaf(xv.x, Dv, a0);
    y[((size_t)b*NTOK + n0 + 1)*DI + d] = fmaf(xv.y, Dv, a1);
    y[((size_t)b*NTOK + n0 + 2)*DI + d] = fmaf(xv.z, Dv, a2);
    y[((size_t)b*NTOK + n0 + 3)*DI + d] = fmaf(xv.w, Dv, a3);
  }
}

// ---------------- launch ----------------
extern "C" void kernel_launch(void* const* d_in, const int* in_sizes, int n_in,
                              void* d_out, int out_size) {
  const float* x    = (const float*)d_in[0];
  const float* sW   = (const float*)d_in[1];
  const float* sb   = (const float*)d_in[2];
  const float* dW   = (const float*)d_in[3];
  const float* db   = (const float*)d_in[4];
  const float* BW   = (const float*)d_in[5];
  const float* CrW  = (const float*)d_in[6];
  const float* CiW  = (const float*)d_in[7];
  const float* Dpar = (const float*)d_in[8];
  const float* Alog = (const float*)d_in[9];
  const float* cwp  = (const float*)d_in[10];
  const float* ra   = (const float*)d_in[11];
  const float* rb   = (const float*)d_in[12];
  float* y = (float*)d_out;

  cudaFuncSetAttribute(ssm_kernel, cudaFuncAttributeMaxDynamicSharedMemorySize,
                       SSM_SMEM_BYTES);

  pack_kernel<<<NOUT, KDIM>>>(sW, sb, dW, db, BW, CrW, CiW);
  transpose_x_kernel<<<dim3(12, 32, 4), dim3(32, 8)>>>(x);
  gemm_kernel<<<dim3(13, 32), 256>>>(x);
  ssm_kernel<<<NB*DI, 256, SSM_SMEM_BYTES>>>(Alog, cwp, ra, rb, Dpar, y);
}